// round 4
// baseline (speedup 1.0000x reference)
#include <cuda_runtime.h>
#include <math.h>

#define BATCH 4
#define CC 64
#define HH 192
#define WW 192
#define NN (HH*WW)
#define NELEM (BATCH*CC*NN)
#define TP 128

__device__ float g_scratch[(size_t)11 * NELEM];
__device__ float g_gram[512*1024];
__device__ float g_normp[512*64];
__device__ float g_attnw[8*1024];

typedef unsigned long long u64;

__device__ __forceinline__ u64 pack2(float a, float b){
  u64 r;
  asm("mov.b64 %0, {%1,%2};" : "=l"(r) : "r"(__float_as_uint(a)), "r"(__float_as_uint(b)));
  return r;
}
__device__ __forceinline__ void unpack2(u64 v, float &a, float &b){
  unsigned lo, hi;
  asm("mov.b64 {%0,%1}, %2;" : "=r"(lo), "=r"(hi) : "l"(v));
  a = __uint_as_float(lo); b = __uint_as_float(hi);
}
__device__ __forceinline__ void ffma2(u64 &d, u64 a, u64 b){
  asm("fma.rn.f32x2 %0, %1, %2, %0;" : "+l"(d) : "l"(a), "l"(b));
}
__device__ __forceinline__ float gelu_f(float x){
  return 0.5f*x*(1.0f + erff(x*0.70710678118654752f));
}

// ================= tiled generic conv1x1: 128 pixels x 64 outputs per CTA =================
// warp w -> outputs [8w, 8w+8) ; lane l -> pixels [4l, 4l+4)
// smem: xs[64][128] (X tile, [c][pix]) + wd[64][128] (duplicated weights wd[c][2o]=wd[c][2o+1]=w[o][c])
__global__ void __launch_bounds__(256,3) k_conv_t(
    const float* __restrict__ ext_in, int in_slice,
    float* __restrict__ ext_out, int out_slice,
    const float* __restrict__ w, int ldw, int woff,
    const float* __restrict__ bias, int accumulate, int do_gelu)
{
  extern __shared__ float sm[];
  float* xs = sm;             // 8192 floats
  float* wd = sm + 64*TP;     // 8192 floats
  const float* xin = (in_slice >= 0) ? (g_scratch + (size_t)in_slice*NELEM) : ext_in;
  float* yout = (out_slice >= 0) ? (g_scratch + (size_t)out_slice*NELEM) : ext_out;
  int tid = threadIdx.x;
  int lane = tid & 31, wid = tid >> 5;

  // stage weights coalesced into padded area of xs: stage[o*65 + c] = w[o][woff+c]
  for (int i = tid; i < 4096; i += 256){
    int o = i >> 6, c = i & 63;
    xs[o*65 + c] = w[o*ldw + woff + c];
  }
  __syncthreads();
  // build duplicated weights (conflict-free reads: stride 65)
  for (int i = tid; i < 4096; i += 256){
    int o = i & 63, c = i >> 6;
    float v = xs[o*65 + c];
    *(float2*)(wd + c*128 + 2*o) = make_float2(v, v);
  }
  __syncthreads();
  // load X tile
  int p0 = blockIdx.x * TP;
  int b = p0 / NN, n0 = p0 - b*NN;
  const float* xb = xin + (size_t)b*(CC*NN) + n0;
  for (int i = tid; i < 2048; i += 256){
    int c = i >> 5, q = i & 31;
    *(float4*)(xs + c*TP + q*4) = *(const float4*)(xb + (size_t)c*NN + q*4);
  }
  __syncthreads();

  u64 acc[16];
  u64 z = pack2(0.f, 0.f);
  #pragma unroll
  for (int i = 0; i < 16; i++) acc[i] = z;
  const float* wrow = wd + wid*16;
  const float* xrow = xs + lane*4;
  #pragma unroll 4
  for (int k = 0; k < 64; k++){
    float4 xv = *(const float4*)(xrow + k*TP);
    u64 x01 = pack2(xv.x, xv.y);
    u64 x23 = pack2(xv.z, xv.w);
    const u64* wp = (const u64*)(wrow + k*128);
    #pragma unroll
    for (int oo = 0; oo < 8; oo++){
      u64 ws = wp[oo];
      ffma2(acc[oo*2+0], ws, x01);
      ffma2(acc[oo*2+1], ws, x23);
    }
  }

  float* yb = yout + (size_t)b*(CC*NN) + n0;
  #pragma unroll
  for (int oo = 0; oo < 8; oo++){
    int o = wid*8 + oo;
    float bv = bias ? __ldg(bias + o) : 0.f;
    float a0,a1,a2,a3;
    unpack2(acc[oo*2],   a0, a1);
    unpack2(acc[oo*2+1], a2, a3);
    a0 += bv; a1 += bv; a2 += bv; a3 += bv;
    float* dst = yb + (size_t)o*NN + lane*4;
    if (accumulate){
      float4 old = *(const float4*)dst;
      a0 += old.x; a1 += old.y; a2 += old.z; a3 += old.w;
    }
    if (do_gelu){ a0=gelu_f(a0); a1=gelu_f(a1); a2=gelu_f(a2); a3=gelu_f(a3); }
    *(float4*)dst = make_float4(a0,a1,a2,a3);
  }
}

// ================= channel-attention apply (block-diag 2x 32x32), tiled =================
__global__ void __launch_bounds__(256,3) k_apply_t(int v_slice, int out_slice)
{
  extern __shared__ float sm[];
  float* xs = sm;            // [64][128]
  float* wd = sm + 64*TP;    // [32][128] dup: wd[k][2o..] = attn[b, o>>5, o&31, k]
  int tid = threadIdx.x;
  int lane = tid & 31, wid = tid >> 5;
  int p0 = blockIdx.x * TP;
  int b = p0 / NN, n0 = p0 - b*NN;
  for (int i = tid; i < 2048; i += 256){
    int o = i & 63, k = i >> 6;
    float v = g_attnw[(size_t)(b*2 + (o>>5))*1024 + (o&31)*32 + k];
    *(float2*)(wd + k*128 + 2*o) = make_float2(v, v);
  }
  const float* xb = g_scratch + (size_t)v_slice*NELEM + (size_t)b*(CC*NN) + n0;
  for (int i = tid; i < 2048; i += 256){
    int c = i >> 5, q = i & 31;
    *(float4*)(xs + c*TP + q*4) = *(const float4*)(xb + (size_t)c*NN + q*4);
  }
  __syncthreads();

  u64 acc[16];
  u64 z = pack2(0.f, 0.f);
  #pragma unroll
  for (int i = 0; i < 16; i++) acc[i] = z;
  const float* wrow = wd + wid*16;
  const float* xrow = xs + (wid>>2)*32*TP + lane*4;   // group base
  #pragma unroll 4
  for (int k = 0; k < 32; k++){
    float4 xv = *(const float4*)(xrow + k*TP);
    u64 x01 = pack2(xv.x, xv.y);
    u64 x23 = pack2(xv.z, xv.w);
    const u64* wp = (const u64*)(wrow + k*128);
    #pragma unroll
    for (int oo = 0; oo < 8; oo++){
      u64 ws = wp[oo];
      ffma2(acc[oo*2+0], ws, x01);
      ffma2(acc[oo*2+1], ws, x23);
    }
  }
  float* yb = g_scratch + (size_t)out_slice*NELEM + (size_t)b*(CC*NN) + n0;
  #pragma unroll
  for (int oo = 0; oo < 8; oo++){
    int o = wid*8 + oo;
    float a0,a1,a2,a3;
    unpack2(acc[oo*2],   a0, a1);
    unpack2(acc[oo*2+1], a2, a3);
    *(float4*)(yb + (size_t)o*NN + lane*4) = make_float4(a0,a1,a2,a3);
  }
}

// ================= depthwise 3x3 + bias + exact GELU =================
__global__ void __launch_bounds__(256) k_dwgelu(
    int in_slice, int out_slice,
    const float* __restrict__ dw_w, const float* __restrict__ dw_b)
{
  int e = blockIdx.x*256 + threadIdx.x;
  const float* tin = g_scratch + (size_t)in_slice*NELEM;
  int n  = e % NN;
  int bc = e / NN;
  int c  = bc & 63;
  int h = n / WW, w = n - h*WW;
  const float* plane = tin + (size_t)bc*NN;
  float s = dw_b[c];
  #pragma unroll
  for (int ky = 0; ky < 3; ky++){
    int hh = h + ky - 1;
    if ((unsigned)hh >= (unsigned)HH) continue;
    #pragma unroll
    for (int kx = 0; kx < 3; kx++){
      int wx = w + kx - 1;
      if ((unsigned)wx >= (unsigned)WW) continue;
      s += dw_w[c*9 + ky*3 + kx] * plane[hh*WW + wx];
    }
  }
  g_scratch[(size_t)out_slice*NELEM + e] = gelu_f(s);
}

// ================= split-K gram + norms =================
__global__ void __launch_bounds__(256) k_gram(int q_slice, int k_slice)
{
  int blk = blockIdx.x;
  int s  = blk & 63;
  int bg = blk >> 6;
  int g = bg & 1, b = bg >> 1;
  int n0 = s * 576;
  const float* qb = g_scratch + (size_t)q_slice*NELEM + (size_t)(b*64 + g*32)*NN;
  const float* kb = g_scratch + (size_t)k_slice*NELEM + (size_t)(b*64 + g*32)*NN;
  __shared__ float qs[32][65];
  __shared__ float ks[32][65];
  int t = threadIdx.x;
  int i = t & 31, jb = t >> 5;
  float acc[4] = {0.f,0.f,0.f,0.f};
  float nacc = 0.f;
  for (int ch = 0; ch < 9; ch++){
    int nb = n0 + ch*64;
    __syncthreads();
    for (int idx = t; idx < 2048; idx += 256){
      int r = idx >> 6, nn = idx & 63;
      qs[r][nn] = qb[(size_t)r*NN + nb + nn];
      ks[r][nn] = kb[(size_t)r*NN + nb + nn];
    }
    __syncthreads();
    #pragma unroll 8
    for (int nn = 0; nn < 64; nn++){
      float qv = qs[i][nn];
      acc[0] += qv * ks[jb*4+0][nn];
      acc[1] += qv * ks[jb*4+1][nn];
      acc[2] += qv * ks[jb*4+2][nn];
      acc[3] += qv * ks[jb*4+3][nn];
    }
    if (t < 32){
      #pragma unroll 8
      for (int nn = 0; nn < 64; nn++){ float v = qs[t][nn]; nacc += v*v; }
    } else if (t < 64){
      int r = t - 32;
      #pragma unroll 8
      for (int nn = 0; nn < 64; nn++){ float v = ks[r][nn]; nacc += v*v; }
    }
  }
  float* Gp = g_gram + (size_t)blk*1024;
  #pragma unroll
  for (int jj = 0; jj < 4; jj++) Gp[i*32 + jb*4 + jj] = acc[jj];
  if (t < 64) g_normp[(size_t)blk*64 + t] = nacc;
}

// ================= gram finalize + softmax =================
__global__ void __launch_bounds__(1024) k_attnsoft(const float* __restrict__ temperature)
{
  int bg = blockIdx.x;
  int g = bg & 1;
  int t = threadIdx.x;
  int i = t >> 5, j = t & 31;
  __shared__ float nq[32], nk[32];
  if (t < 64){
    float s = 0.f;
    for (int ss = 0; ss < 64; ss++) s += g_normp[(size_t)(bg*64 + ss)*64 + t];
    float nv = fmaxf(sqrtf(s), 1e-12f);
    if (t < 32) nq[t] = nv; else nk[t-32] = nv;
  }
  float G = 0.f;
  for (int ss = 0; ss < 64; ss++) G += g_gram[(size_t)(bg*64 + ss)*1024 + t];
  __syncthreads();
  float logit = G / (nq[i]*nk[j]) * temperature[g];
  float m = logit;
  #pragma unroll
  for (int o = 16; o > 0; o >>= 1) m = fmaxf(m, __shfl_xor_sync(0xffffffffu, m, o));
  float e = __expf(logit - m);
  float ssum = e;
  #pragma unroll
  for (int o = 16; o > 0; o >>= 1) ssum += __shfl_xor_sync(0xffffffffu, ssum, o);
  g_attnw[(size_t)bg*1024 + t] = e / ssum;
}

// ================= line attention (row; col via transposed planes) =================
__global__ void __launch_bounds__(192, 2) k_lineattn(
    int q_slice, int k_slice, int v_slice, int x_slice, int out_slice,
    const float* __restrict__ gamma_p)
{
  extern __shared__ float smem[];
  float* Ksh = smem;                 // [192][68], j-major (68*4B = 272B, 16B aligned)
  float* Vsh = smem + 192*68;
  int blk = blockIdx.x;
  int h = blk % HH;
  int b = blk / HH;
  size_t base = (size_t)b*(CC*NN) + (size_t)h*WW;
  const float* Qb = g_scratch + (size_t)q_slice*NELEM + base;
  const float* Kb = g_scratch + (size_t)k_slice*NELEM + base;
  const float* Vb = g_scratch + (size_t)v_slice*NELEM + base;
  const float* Xb = g_scratch + (size_t)x_slice*NELEM + base;
  float* Ob = g_scratch + (size_t)out_slice*NELEM + base;
  int t = threadIdx.x;
  for (int idx = t; idx < 64*192; idx += 192){
    int c = idx / 192;
    int j = idx - c*192;
    Ksh[j*68 + c] = Kb[(size_t)c*NN + j];
    Vsh[j*68 + c] = Vb[(size_t)c*NN + j];
  }
  u64 q2[32];
  #pragma unroll
  for (int cc = 0; cc < 32; cc++)
    q2[cc] = pack2(Qb[(size_t)(2*cc)*NN + t], Qb[(size_t)(2*cc+1)*NN + t]);
  __syncthreads();
  u64 z = pack2(0.f, 0.f);
  float sv[192];
  float m = -1e30f;
  #pragma unroll 1
  for (int j = 0; j < 192; j++){
    const float4* kr4 = (const float4*)(Ksh + j*68);
    u64 a0 = z, a1 = z, a2 = z, a3 = z;
    #pragma unroll
    for (int cc = 0; cc < 8; cc++){
      float4 kv0 = kr4[2*cc];
      float4 kv1 = kr4[2*cc+1];
      ffma2(a0, q2[4*cc+0], pack2(kv0.x, kv0.y));
      ffma2(a1, q2[4*cc+1], pack2(kv0.z, kv0.w));
      ffma2(a2, q2[4*cc+2], pack2(kv1.x, kv1.y));
      ffma2(a3, q2[4*cc+3], pack2(kv1.z, kv1.w));
    }
    float x0,y0,x1,y1,x2,y2,x3,y3;
    unpack2(a0,x0,y0); unpack2(a1,x1,y1); unpack2(a2,x2,y2); unpack2(a3,x3,y3);
    float s = ((x0+y0)+(x1+y1)) + ((x2+y2)+(x3+y3));
    sv[j] = s;
    m = fmaxf(m, s);
  }
  float l = 0.f;
  u64 acc[32];
  #pragma unroll
  for (int cc = 0; cc < 32; cc++) acc[cc] = z;
  #pragma unroll 1
  for (int j = 0; j < 192; j++){
    float p = __expf(sv[j] - m);
    l += p;
    u64 ps = pack2(p, p);
    const float4* vr4 = (const float4*)(Vsh + j*68);
    #pragma unroll
    for (int cc = 0; cc < 16; cc++){
      float4 vv = vr4[cc];
      ffma2(acc[2*cc],   ps, pack2(vv.x, vv.y));
      ffma2(acc[2*cc+1], ps, pack2(vv.z, vv.w));
    }
  }
  float gam = gamma_p[0] / l;
  #pragma unroll
  for (int cc = 0; cc < 32; cc++){
    float a0, a1; unpack2(acc[cc], a0, a1);
    Ob[(size_t)(2*cc)*NN + t]   = gam*a0 + Xb[(size_t)(2*cc)*NN + t];
    Ob[(size_t)(2*cc+1)*NN + t] = gam*a1 + Xb[(size_t)(2*cc+1)*NN + t];
  }
}

// ================= per-plane 192x192 transpose =================
__global__ void k_transpose(int in_slice, int out_slice)
{
  __shared__ float tile[32][33];
  const float* in = g_scratch + (size_t)in_slice*NELEM + (size_t)blockIdx.z*NN;
  float* out      = g_scratch + (size_t)out_slice*NELEM + (size_t)blockIdx.z*NN;
  int x0 = blockIdx.x*32, y0 = blockIdx.y*32;
  int tx = threadIdx.x, ty = threadIdx.y;
  #pragma unroll
  for (int k = 0; k < 32; k += 8)
    tile[ty+k][tx] = in[(size_t)(y0+ty+k)*WW + x0+tx];
  __syncthreads();
  #pragma unroll
  for (int k = 0; k < 32; k += 8)
    out[(size_t)(x0+ty+k)*HH + y0+tx] = tile[tx][ty+k];
}

extern "C" void kernel_launch(void* const* d_in, const int* in_sizes, int n_in,
                              void* d_out, int out_size)
{
  const float* x    = (const float*)d_in[0];
  const float* pw_w = (const float*)d_in[1];
  const float* dw_w = (const float*)d_in[2];
  const float* dw_b = (const float*)d_in[3];
  const float* c2w  = (const float*)d_in[4];
  const float* c2b  = (const float*)d_in[5];
  const float* c0w  = (const float*)d_in[6];
  const float* c0b  = (const float*)d_in[7];
  const float* aq   = (const float*)d_in[8];
  const float* ak   = (const float*)d_in[9];
  const float* av   = (const float*)d_in[10];
  const float* ap   = (const float*)d_in[11];
  const float* temp = (const float*)d_in[12];
  const float* rq   = (const float*)d_in[13];
  const float* rk   = (const float*)d_in[14];
  const float* rv   = (const float*)d_in[15];
  const float* rg   = (const float*)d_in[16];
  const float* cq   = (const float*)d_in[17];
  const float* ck   = (const float*)d_in[18];
  const float* cv   = (const float*)d_in[19];
  const float* cg   = (const float*)d_in[20];
  const float* fw   = (const float*)d_in[21];
  const float* fb   = (const float*)d_in[22];
  float* out = (float*)d_out;

  const int TILES = (BATCH*NN)/TP;            // 1152
  const int SM_CONV  = (64*TP + 64*TP)*4;     // 65536
  const int SM_APPLY = (64*TP + 32*TP)*4;     // 49152
  const int SMEM_LA  = 2*192*68*4;            // 104448
  cudaFuncSetAttribute(k_conv_t,  cudaFuncAttributeMaxDynamicSharedMemorySize, SM_CONV);
  cudaFuncSetAttribute(k_apply_t, cudaFuncAttributeMaxDynamicSharedMemorySize, SM_APPLY);
  cudaFuncSetAttribute(k_lineattn,cudaFuncAttributeMaxDynamicSharedMemorySize, SMEM_LA);

  // t = pw(x)
  k_conv_t<<<TILES,256,SM_CONV>>>(x, -1, nullptr, 0, pw_w, 64, 0, nullptr, 0, 0);
  // gelu(dw(t)+b)
  k_dwgelu<<<NELEM/256,256>>>(0, 1, dw_w, dw_b);
  // x1 = conv2(u)+b2 + conv0(x)+b0
  k_conv_t<<<TILES,256,SM_CONV>>>(nullptr, 1, nullptr, 2, c2w, 64, 0, c2b, 0, 0);
  k_conv_t<<<TILES,256,SM_CONV>>>(x, -1, nullptr, 2, c0w, 64, 0, c0b, 1, 0);

  // channel attention
  k_conv_t<<<TILES,256,SM_CONV>>>(nullptr, 2, nullptr, 3, aq, 64, 0, nullptr, 0, 0);
  k_conv_t<<<TILES,256,SM_CONV>>>(nullptr, 2, nullptr, 4, ak, 64, 0, nullptr, 0, 0);
  k_conv_t<<<TILES,256,SM_CONV>>>(nullptr, 2, nullptr, 5, av, 64, 0, nullptr, 0, 0);
  k_gram<<<512,256>>>(3, 4);
  k_attnsoft<<<8,1024>>>(temp);
  k_apply_t<<<TILES,256,SM_APPLY>>>(5, 6);
  k_conv_t<<<TILES,256,SM_CONV>>>(nullptr, 6, nullptr, 7, ap, 64, 0, nullptr, 0, 0);  // out1

  // row attention
  k_conv_t<<<TILES,256,SM_CONV>>>(nullptr, 2, nullptr, 3, rq, 64, 0, nullptr, 0, 0);
  k_conv_t<<<TILES,256,SM_CONV>>>(nullptr, 2, nullptr, 4, rk, 64, 0, nullptr, 0, 0);
  k_conv_t<<<TILES,256,SM_CONV>>>(nullptr, 7, nullptr, 5, rv, 64, 0, nullptr, 0, 0);
  k_lineattn<<<768,192,SMEM_LA>>>(3, 4, 5, 2, 8, rg);   // out2

  // col attention (transposed planes)
  k_conv_t<<<TILES,256,SM_CONV>>>(nullptr, 2, nullptr, 3, cq, 64, 0, nullptr, 0, 0);
  k_conv_t<<<TILES,256,SM_CONV>>>(nullptr, 2, nullptr, 4, ck, 64, 0, nullptr, 0, 0);
  k_conv_t<<<TILES,256,SM_CONV>>>(nullptr, 7, nullptr, 5, cv, 64, 0, nullptr, 0, 0);
  dim3 tg(6,6,BATCH*CC), tb(32,8);
  k_transpose<<<tg,tb>>>(3, 0);
  k_transpose<<<tg,tb>>>(4, 1);
  k_transpose<<<tg,tb>>>(5, 6);
  k_transpose<<<tg,tb>>>(2, 10);
  k_lineattn<<<768,192,SMEM_LA>>>(0, 1, 6, 10, 3, cg);  // out3^T
  k_transpose<<<tg,tb>>>(3, 9);                         // out3

  // final fuse conv (3 accumulate passes over [out1;out2;out3]), GELU on last
  k_conv_t<<<TILES,256,SM_CONV>>>(nullptr, 7, out, -1, fw, 192, 0,   nullptr, 0, 0);
  k_conv_t<<<TILES,256,SM_CONV>>>(nullptr, 8, out, -1, fw, 192, 64,  nullptr, 1, 0);
  k_conv_t<<<TILES,256,SM_CONV>>>(nullptr, 9, out, -1, fw, 192, 128, fb,      1, 1);
}

// round 5
// speedup vs baseline: 1.2261x; 1.2261x over previous
#include <cuda_runtime.h>
#include <math.h>

#define BATCH 4
#define CC 64
#define HH 192
#define WW 192
#define NN (HH*WW)
#define NELEM (BATCH*CC*NN)
#define TP 128

__device__ float g_scratch[(size_t)11 * NELEM];
__device__ float g_gram[512*1024];
__device__ float g_normp[512*64];
__device__ float g_attnw[8*1024];

typedef unsigned long long u64;

__device__ __forceinline__ u64 pack2(float a, float b){
  u64 r;
  asm("mov.b64 %0, {%1,%2};" : "=l"(r) : "r"(__float_as_uint(a)), "r"(__float_as_uint(b)));
  return r;
}
__device__ __forceinline__ void unpack2(u64 v, float &a, float &b){
  unsigned lo, hi;
  asm("mov.b64 {%0,%1}, %2;" : "=r"(lo), "=r"(hi) : "l"(v));
  a = __uint_as_float(lo); b = __uint_as_float(hi);
}
__device__ __forceinline__ void ffma2(u64 &d, u64 a, u64 b){
  asm("fma.rn.f32x2 %0, %1, %2, %0;" : "+l"(d) : "l"(a), "l"(b));
}
__device__ __forceinline__ float gelu_f(float x){
  return 0.5f*x*(1.0f + erff(x*0.70710678118654752f));
}

// epilogue: acc[pp*4+px] = (y[o=base+2pp], y[o=base+2pp+1]) at pixel px
__device__ __forceinline__ void store8(
    u64* acc, float* yb, int obase, int lane,
    const float* bias, const float* bias2, int do_gelu)
{
  #pragma unroll
  for (int pp = 0; pp < 4; pp++){
    float lo0,hi0,lo1,hi1,lo2,hi2,lo3,hi3;
    unpack2(acc[pp*4+0], lo0, hi0);
    unpack2(acc[pp*4+1], lo1, hi1);
    unpack2(acc[pp*4+2], lo2, hi2);
    unpack2(acc[pp*4+3], lo3, hi3);
    int o = obase + 2*pp;
    float b0 = bias ? bias[o] : 0.f;
    float b1 = bias ? bias[o+1] : 0.f;
    if (bias2){ b0 += bias2[o]; b1 += bias2[o+1]; }
    lo0+=b0; lo1+=b0; lo2+=b0; lo3+=b0;
    hi0+=b1; hi1+=b1; hi2+=b1; hi3+=b1;
    if (do_gelu){
      lo0=gelu_f(lo0); lo1=gelu_f(lo1); lo2=gelu_f(lo2); lo3=gelu_f(lo3);
      hi0=gelu_f(hi0); hi1=gelu_f(hi1); hi2=gelu_f(hi2); hi3=gelu_f(hi3);
    }
    *(float4*)(yb + (size_t)o*NN     + lane*4) = make_float4(lo0,lo1,lo2,lo3);
    *(float4*)(yb + (size_t)(o+1)*NN + lane*4) = make_float4(hi0,hi1,hi2,hi3);
  }
}

// ================= single-matrix conv1x1 (64->64), 128px tile =================
__global__ void __launch_bounds__(256,3) k_conv1(
    const float* __restrict__ ext_in, int in_slice,
    float* __restrict__ ext_out, int out_slice,
    const float* __restrict__ w, int ldw,
    const float* __restrict__ bias, int do_gelu)
{
  extern __shared__ float sm[];
  float* xs = sm;              // [64][128]
  float* ws = sm + 64*TP;      // [64][68]  ws[c*68+o] = w[o][c]
  int tid = threadIdx.x, lane = tid & 31, wid = tid >> 5;
  const float* xin = (in_slice >= 0) ? g_scratch + (size_t)in_slice*NELEM : ext_in;
  float* yout = (out_slice >= 0) ? g_scratch + (size_t)out_slice*NELEM : ext_out;
  for (int i = tid; i < 4096; i += 256){
    int c = i & 63, o = i >> 6;
    ws[c*68 + o] = w[o*ldw + c];
  }
  int p0 = blockIdx.x * TP;
  int b = p0 / NN, n0 = p0 - b*NN;
  const float* xb = xin + (size_t)b*(CC*NN) + n0;
  for (int i = tid; i < 2048; i += 256){
    int c = i >> 5, q = i & 31;
    *(float4*)(xs + c*TP + q*4) = *(const float4*)(xb + (size_t)c*NN + q*4);
  }
  __syncthreads();
  u64 acc[16];
  u64 z = pack2(0.f, 0.f);
  #pragma unroll
  for (int i = 0; i < 16; i++) acc[i] = z;
  const float* xrow = xs + lane*4;
  const float* wrow = ws + wid*8;
  #pragma unroll 8
  for (int k = 0; k < 64; k++){
    float4 xv = *(const float4*)(xrow + k*TP);
    u64 s0 = pack2(xv.x, xv.x), s1 = pack2(xv.y, xv.y);
    u64 s2 = pack2(xv.z, xv.z), s3 = pack2(xv.w, xv.w);
    ulonglong2 wv0 = *(const ulonglong2*)(wrow + k*68);
    ulonglong2 wv1 = *(const ulonglong2*)(wrow + k*68 + 4);
    ffma2(acc[0],  wv0.x, s0); ffma2(acc[1],  wv0.x, s1); ffma2(acc[2],  wv0.x, s2); ffma2(acc[3],  wv0.x, s3);
    ffma2(acc[4],  wv0.y, s0); ffma2(acc[5],  wv0.y, s1); ffma2(acc[6],  wv0.y, s2); ffma2(acc[7],  wv0.y, s3);
    ffma2(acc[8],  wv1.x, s0); ffma2(acc[9],  wv1.x, s1); ffma2(acc[10], wv1.x, s2); ffma2(acc[11], wv1.x, s3);
    ffma2(acc[12], wv1.y, s0); ffma2(acc[13], wv1.y, s1); ffma2(acc[14], wv1.y, s2); ffma2(acc[15], wv1.y, s3);
  }
  float* yb = yout + (size_t)b*(CC*NN) + n0;
  store8(acc, yb, wid*8, lane, bias, nullptr, do_gelu);
}

// ================= dual-output conv1x1: one input, two weight matrices =================
__global__ void __launch_bounds__(256,2) k_conv2(
    int in_slice, int outA, int outB,
    const float* __restrict__ wA, const float* __restrict__ wB)
{
  extern __shared__ float sm[];
  float* xs  = sm;               // [64][128]
  float* wsA = sm + 64*TP;       // [64][68]
  float* wsB = wsA + 64*68;
  int tid = threadIdx.x, lane = tid & 31, wid = tid >> 5;
  for (int i = tid; i < 4096; i += 256){
    int c = i & 63, o = i >> 6;
    wsA[c*68 + o] = wA[o*64 + c];
    wsB[c*68 + o] = wB[o*64 + c];
  }
  int p0 = blockIdx.x * TP;
  int b = p0 / NN, n0 = p0 - b*NN;
  const float* xb = g_scratch + (size_t)in_slice*NELEM + (size_t)b*(CC*NN) + n0;
  for (int i = tid; i < 2048; i += 256){
    int c = i >> 5, q = i & 31;
    *(float4*)(xs + c*TP + q*4) = *(const float4*)(xb + (size_t)c*NN + q*4);
  }
  __syncthreads();
  u64 accA[16], accB[16];
  u64 z = pack2(0.f, 0.f);
  #pragma unroll
  for (int i = 0; i < 16; i++){ accA[i] = z; accB[i] = z; }
  const float* xrow = xs + lane*4;
  const float* wra = wsA + wid*8;
  const float* wrb = wsB + wid*8;
  #pragma unroll 4
  for (int k = 0; k < 64; k++){
    float4 xv = *(const float4*)(xrow + k*TP);
    u64 s0 = pack2(xv.x, xv.x), s1 = pack2(xv.y, xv.y);
    u64 s2 = pack2(xv.z, xv.z), s3 = pack2(xv.w, xv.w);
    ulonglong2 a0 = *(const ulonglong2*)(wra + k*68);
    ulonglong2 a1 = *(const ulonglong2*)(wra + k*68 + 4);
    ulonglong2 b0 = *(const ulonglong2*)(wrb + k*68);
    ulonglong2 b1 = *(const ulonglong2*)(wrb + k*68 + 4);
    ffma2(accA[0],  a0.x, s0); ffma2(accA[1],  a0.x, s1); ffma2(accA[2],  a0.x, s2); ffma2(accA[3],  a0.x, s3);
    ffma2(accA[4],  a0.y, s0); ffma2(accA[5],  a0.y, s1); ffma2(accA[6],  a0.y, s2); ffma2(accA[7],  a0.y, s3);
    ffma2(accA[8],  a1.x, s0); ffma2(accA[9],  a1.x, s1); ffma2(accA[10], a1.x, s2); ffma2(accA[11], a1.x, s3);
    ffma2(accA[12], a1.y, s0); ffma2(accA[13], a1.y, s1); ffma2(accA[14], a1.y, s2); ffma2(accA[15], a1.y, s3);
    ffma2(accB[0],  b0.x, s0); ffma2(accB[1],  b0.x, s1); ffma2(accB[2],  b0.x, s2); ffma2(accB[3],  b0.x, s3);
    ffma2(accB[4],  b0.y, s0); ffma2(accB[5],  b0.y, s1); ffma2(accB[6],  b0.y, s2); ffma2(accB[7],  b0.y, s3);
    ffma2(accB[8],  b1.x, s0); ffma2(accB[9],  b1.x, s1); ffma2(accB[10], b1.x, s2); ffma2(accB[11], b1.x, s3);
    ffma2(accB[12], b1.y, s0); ffma2(accB[13], b1.y, s1); ffma2(accB[14], b1.y, s2); ffma2(accB[15], b1.y, s3);
  }
  size_t boff = (size_t)b*(CC*NN) + n0;
  store8(accA, g_scratch + (size_t)outA*NELEM + boff, wid*8, lane, nullptr, nullptr, 0);
  store8(accB, g_scratch + (size_t)outB*NELEM + boff, wid*8, lane, nullptr, nullptr, 0);
}

// ================= dual-input conv1x1: y = wA@inA + bA + wB@inB + bB =================
__global__ void __launch_bounds__(256,2) k_convDI(
    int inA_slice, const float* __restrict__ extB, int out_slice,
    const float* __restrict__ wA, const float* __restrict__ bA,
    const float* __restrict__ wB, const float* __restrict__ bB)
{
  extern __shared__ float sm[];
  float* xsA = sm;               // [64][128]
  float* xsB = xsA + 64*TP;
  float* wsA = xsB + 64*TP;      // [64][68]
  float* wsB = wsA + 64*68;
  int tid = threadIdx.x, lane = tid & 31, wid = tid >> 5;
  for (int i = tid; i < 4096; i += 256){
    int c = i & 63, o = i >> 6;
    wsA[c*68 + o] = wA[o*64 + c];
    wsB[c*68 + o] = wB[o*64 + c];
  }
  int p0 = blockIdx.x * TP;
  int b = p0 / NN, n0 = p0 - b*NN;
  size_t boff = (size_t)b*(CC*NN) + n0;
  const float* xa = g_scratch + (size_t)inA_slice*NELEM + boff;
  const float* xbp = extB + boff;
  for (int i = tid; i < 2048; i += 256){
    int c = i >> 5, q = i & 31;
    *(float4*)(xsA + c*TP + q*4) = *(const float4*)(xa  + (size_t)c*NN + q*4);
    *(float4*)(xsB + c*TP + q*4) = *(const float4*)(xbp + (size_t)c*NN + q*4);
  }
  __syncthreads();
  u64 acc[16];
  u64 z = pack2(0.f, 0.f);
  #pragma unroll
  for (int i = 0; i < 16; i++) acc[i] = z;
  const float* xra = xsA + lane*4;
  const float* xrb = xsB + lane*4;
  const float* wra = wsA + wid*8;
  const float* wrb = wsB + wid*8;
  #pragma unroll 4
  for (int k = 0; k < 64; k++){
    float4 xv = *(const float4*)(xra + k*TP);
    u64 s0 = pack2(xv.x, xv.x), s1 = pack2(xv.y, xv.y);
    u64 s2 = pack2(xv.z, xv.z), s3 = pack2(xv.w, xv.w);
    ulonglong2 a0 = *(const ulonglong2*)(wra + k*68);
    ulonglong2 a1 = *(const ulonglong2*)(wra + k*68 + 4);
    ffma2(acc[0],  a0.x, s0); ffma2(acc[1],  a0.x, s1); ffma2(acc[2],  a0.x, s2); ffma2(acc[3],  a0.x, s3);
    ffma2(acc[4],  a0.y, s0); ffma2(acc[5],  a0.y, s1); ffma2(acc[6],  a0.y, s2); ffma2(acc[7],  a0.y, s3);
    ffma2(acc[8],  a1.x, s0); ffma2(acc[9],  a1.x, s1); ffma2(acc[10], a1.x, s2); ffma2(acc[11], a1.x, s3);
    ffma2(acc[12], a1.y, s0); ffma2(acc[13], a1.y, s1); ffma2(acc[14], a1.y, s2); ffma2(acc[15], a1.y, s3);
    float4 yv = *(const float4*)(xrb + k*TP);
    u64 t0 = pack2(yv.x, yv.x), t1 = pack2(yv.y, yv.y);
    u64 t2 = pack2(yv.z, yv.z), t3 = pack2(yv.w, yv.w);
    ulonglong2 b0 = *(const ulonglong2*)(wrb + k*68);
    ulonglong2 b1 = *(const ulonglong2*)(wrb + k*68 + 4);
    ffma2(acc[0],  b0.x, t0); ffma2(acc[1],  b0.x, t1); ffma2(acc[2],  b0.x, t2); ffma2(acc[3],  b0.x, t3);
    ffma2(acc[4],  b0.y, t0); ffma2(acc[5],  b0.y, t1); ffma2(acc[6],  b0.y, t2); ffma2(acc[7],  b0.y, t3);
    ffma2(acc[8],  b1.x, t0); ffma2(acc[9],  b1.x, t1); ffma2(acc[10], b1.x, t2); ffma2(acc[11], b1.x, t3);
    ffma2(acc[12], b1.y, t0); ffma2(acc[13], b1.y, t1); ffma2(acc[14], b1.y, t2); ffma2(acc[15], b1.y, t3);
  }
  store8(acc, g_scratch + (size_t)out_slice*NELEM + boff, wid*8, lane, bA, bB, 0);
}

// ================= final conv 192->64 (3 slices) + GELU =================
__global__ void __launch_bounds__(256,2) k_final3(
    int s1, int s2, int s3,
    const float* __restrict__ w, const float* __restrict__ bias,
    float* __restrict__ out)
{
  extern __shared__ float sm[];
  float* xs = sm;              // [64][128]
  float* ws = sm + 64*TP;      // [192][68]
  int tid = threadIdx.x, lane = tid & 31, wid = tid >> 5;
  for (int i = tid; i < 12288; i += 256){
    int o = i / 192, c = i - o*192;
    ws[c*68 + o] = w[o*192 + c];
  }
  int p0 = blockIdx.x * TP;
  int b = p0 / NN, n0 = p0 - b*NN;
  size_t boff = (size_t)b*(CC*NN) + n0;
  u64 acc[16];
  u64 z = pack2(0.f, 0.f);
  #pragma unroll
  for (int i = 0; i < 16; i++) acc[i] = z;
  const float* xrow = xs + lane*4;
  int slices[3] = {s1, s2, s3};
  for (int p = 0; p < 3; p++){
    const float* xb = g_scratch + (size_t)slices[p]*NELEM + boff;
    __syncthreads();
    for (int i = tid; i < 2048; i += 256){
      int c = i >> 5, q = i & 31;
      *(float4*)(xs + c*TP + q*4) = *(const float4*)(xb + (size_t)c*NN + q*4);
    }
    __syncthreads();
    const float* wrow = ws + (p*64)*68 + wid*8;
    #pragma unroll 8
    for (int k = 0; k < 64; k++){
      float4 xv = *(const float4*)(xrow + k*TP);
      u64 s0 = pack2(xv.x, xv.x), sA = pack2(xv.y, xv.y);
      u64 s2v = pack2(xv.z, xv.z), s3v = pack2(xv.w, xv.w);
      ulonglong2 wv0 = *(const ulonglong2*)(wrow + k*68);
      ulonglong2 wv1 = *(const ulonglong2*)(wrow + k*68 + 4);
      ffma2(acc[0],  wv0.x, s0); ffma2(acc[1],  wv0.x, sA); ffma2(acc[2],  wv0.x, s2v); ffma2(acc[3],  wv0.x, s3v);
      ffma2(acc[4],  wv0.y, s0); ffma2(acc[5],  wv0.y, sA); ffma2(acc[6],  wv0.y, s2v); ffma2(acc[7],  wv0.y, s3v);
      ffma2(acc[8],  wv1.x, s0); ffma2(acc[9],  wv1.x, sA); ffma2(acc[10], wv1.x, s2v); ffma2(acc[11], wv1.x, s3v);
      ffma2(acc[12], wv1.y, s0); ffma2(acc[13], wv1.y, sA); ffma2(acc[14], wv1.y, s2v); ffma2(acc[15], wv1.y, s3v);
    }
  }
  store8(acc, out + boff, wid*8, lane, bias, nullptr, 1);
}

// ================= channel-attention apply (block-diag 2x 32x32) =================
__global__ void __launch_bounds__(256,3) k_apply_t(int v_slice, int out_slice)
{
  extern __shared__ float sm[];
  float* xs = sm;             // [64][128]
  float* ws = sm + 64*TP;     // [2*32][36] : ws[(g*32+k)*36 + o] = attn[b,g,o,k]
  int tid = threadIdx.x, lane = tid & 31, wid = tid >> 5;
  int p0 = blockIdx.x * TP;
  int b = p0 / NN, n0 = p0 - b*NN;
  for (int i = tid; i < 2048; i += 256){
    int g = i >> 10, rem = i & 1023;
    int o = rem >> 5, k = rem & 31;
    ws[(g*32 + k)*36 + o] = g_attnw[(size_t)(b*2+g)*1024 + o*32 + k];
  }
  const float* xb = g_scratch + (size_t)v_slice*NELEM + (size_t)b*(CC*NN) + n0;
  for (int i = tid; i < 2048; i += 256){
    int c = i >> 5, q = i & 31;
    *(float4*)(xs + c*TP + q*4) = *(const float4*)(xb + (size_t)c*NN + q*4);
  }
  __syncthreads();
  int g = wid >> 2;
  int ow = (wid & 3) * 8;
  u64 acc[16];
  u64 z = pack2(0.f, 0.f);
  #pragma unroll
  for (int i = 0; i < 16; i++) acc[i] = z;
  const float* xrow = xs + g*32*TP + lane*4;
  const float* wrow = ws + g*32*36 + ow;
  #pragma unroll 8
  for (int k = 0; k < 32; k++){
    float4 xv = *(const float4*)(xrow + k*TP);
    u64 s0 = pack2(xv.x, xv.x), s1 = pack2(xv.y, xv.y);
    u64 s2 = pack2(xv.z, xv.z), s3 = pack2(xv.w, xv.w);
    ulonglong2 wv0 = *(const ulonglong2*)(wrow + k*36);
    ulonglong2 wv1 = *(const ulonglong2*)(wrow + k*36 + 4);
    ffma2(acc[0],  wv0.x, s0); ffma2(acc[1],  wv0.x, s1); ffma2(acc[2],  wv0.x, s2); ffma2(acc[3],  wv0.x, s3);
    ffma2(acc[4],  wv0.y, s0); ffma2(acc[5],  wv0.y, s1); ffma2(acc[6],  wv0.y, s2); ffma2(acc[7],  wv0.y, s3);
    ffma2(acc[8],  wv1.x, s0); ffma2(acc[9],  wv1.x, s1); ffma2(acc[10], wv1.x, s2); ffma2(acc[11], wv1.x, s3);
    ffma2(acc[12], wv1.y, s0); ffma2(acc[13], wv1.y, s1); ffma2(acc[14], wv1.y, s2); ffma2(acc[15], wv1.y, s3);
  }
  float* yb = g_scratch + (size_t)out_slice*NELEM + (size_t)b*(CC*NN) + n0;
  store8(acc, yb, g*32 + ow, lane, nullptr, nullptr, 0);
}

// ================= depthwise 3x3 + bias + exact GELU =================
__global__ void __launch_bounds__(256) k_dwgelu(
    int in_slice, int out_slice,
    const float* __restrict__ dw_w, const float* __restrict__ dw_b)
{
  int e = blockIdx.x*256 + threadIdx.x;
  const float* tin = g_scratch + (size_t)in_slice*NELEM;
  int n  = e % NN;
  int bc = e / NN;
  int c  = bc & 63;
  int h = n / WW, w = n - h*WW;
  const float* plane = tin + (size_t)bc*NN;
  float s = dw_b[c];
  #pragma unroll
  for (int ky = 0; ky < 3; ky++){
    int hh = h + ky - 1;
    if ((unsigned)hh >= (unsigned)HH) continue;
    #pragma unroll
    for (int kx = 0; kx < 3; kx++){
      int wx = w + kx - 1;
      if ((unsigned)wx >= (unsigned)WW) continue;
      s += dw_w[c*9 + ky*3 + kx] * plane[hh*WW + wx];
    }
  }
  g_scratch[(size_t)out_slice*NELEM + e] = gelu_f(s);
}

// ================= split-K gram + norms =================
__global__ void __launch_bounds__(256) k_gram(int q_slice, int k_slice)
{
  int blk = blockIdx.x;
  int s  = blk & 63;
  int bg = blk >> 6;
  int g = bg & 1, b = bg >> 1;
  int n0 = s * 576;
  const float* qb = g_scratch + (size_t)q_slice*NELEM + (size_t)(b*64 + g*32)*NN;
  const float* kb = g_scratch + (size_t)k_slice*NELEM + (size_t)(b*64 + g*32)*NN;
  __shared__ float qs[32][65];
  __shared__ float ks[32][65];
  int t = threadIdx.x;
  int i = t & 31, jb = t >> 5;
  float acc[4] = {0.f,0.f,0.f,0.f};
  float nacc = 0.f;
  for (int ch = 0; ch < 9; ch++){
    int nb = n0 + ch*64;
    __syncthreads();
    for (int idx = t; idx < 2048; idx += 256){
      int r = idx >> 6, nn = idx & 63;
      qs[r][nn] = qb[(size_t)r*NN + nb + nn];
      ks[r][nn] = kb[(size_t)r*NN + nb + nn];
    }
    __syncthreads();
    #pragma unroll 8
    for (int nn = 0; nn < 64; nn++){
      float qv = qs[i][nn];
      acc[0] += qv * ks[jb*4+0][nn];
      acc[1] += qv * ks[jb*4+1][nn];
      acc[2] += qv * ks[jb*4+2][nn];
      acc[3] += qv * ks[jb*4+3][nn];
    }
    if (t < 32){
      #pragma unroll 8
      for (int nn = 0; nn < 64; nn++){ float v = qs[t][nn]; nacc += v*v; }
    } else if (t < 64){
      int r = t - 32;
      #pragma unroll 8
      for (int nn = 0; nn < 64; nn++){ float v = ks[r][nn]; nacc += v*v; }
    }
  }
  float* Gp = g_gram + (size_t)blk*1024;
  #pragma unroll
  for (int jj = 0; jj < 4; jj++) Gp[i*32 + jb*4 + jj] = acc[jj];
  if (t < 64) g_normp[(size_t)blk*64 + t] = nacc;
}

// ================= gram finalize + softmax =================
__global__ void __launch_bounds__(1024) k_attnsoft(const float* __restrict__ temperature)
{
  int bg = blockIdx.x;
  int g = bg & 1;
  int t = threadIdx.x;
  int i = t >> 5, j = t & 31;
  __shared__ float nq[32], nk[32];
  if (t < 64){
    float s = 0.f;
    for (int ss = 0; ss < 64; ss++) s += g_normp[(size_t)(bg*64 + ss)*64 + t];
    float nv = fmaxf(sqrtf(s), 1e-12f);
    if (t < 32) nq[t] = nv; else nk[t-32] = nv;
  }
  float G = 0.f;
  for (int ss = 0; ss < 64; ss++) G += g_gram[(size_t)(bg*64 + ss)*1024 + t];
  __syncthreads();
  float logit = G / (nq[i]*nk[j]) * temperature[g];
  float m = logit;
  #pragma unroll
  for (int o = 16; o > 0; o >>= 1) m = fmaxf(m, __shfl_xor_sync(0xffffffffu, m, o));
  float e = __expf(logit - m);
  float ssum = e;
  #pragma unroll
  for (int o = 16; o > 0; o >>= 1) ssum += __shfl_xor_sync(0xffffffffu, ssum, o);
  g_attnw[(size_t)bg*1024 + t] = e / ssum;
}

// ================= line attention, single-pass (no-max exp; logits bounded) =================
__global__ void __launch_bounds__(192, 2) k_lineattn(
    int q_slice, int k_slice, int v_slice, int x_slice, int out_slice,
    const float* __restrict__ gamma_p)
{
  extern __shared__ float smem[];
  float* Ksh = smem;                 // [192][68], j-major
  float* Vsh = smem + 192*68;
  int blk = blockIdx.x;
  int h = blk % HH;
  int b = blk / HH;
  size_t base = (size_t)b*(CC*NN) + (size_t)h*WW;
  const float* Qb = g_scratch + (size_t)q_slice*NELEM + base;
  const float* Kb = g_scratch + (size_t)k_slice*NELEM + base;
  const float* Vb = g_scratch + (size_t)v_slice*NELEM + base;
  const float* Xb = g_scratch + (size_t)x_slice*NELEM + base;
  float* Ob = g_scratch + (size_t)out_slice*NELEM + base;
  int t = threadIdx.x;
  for (int idx = t; idx < 64*192; idx += 192){
    int c = idx / 192;
    int j = idx - c*192;
    Ksh[j*68 + c] = Kb[(size_t)c*NN + j];
    Vsh[j*68 + c] = Vb[(size_t)c*NN + j];
  }
  u64 q2[32];
  #pragma unroll
  for (int cc = 0; cc < 32; cc++)
    q2[cc] = pack2(Qb[(size_t)(2*cc)*NN + t], Qb[(size_t)(2*cc+1)*NN + t]);
  __syncthreads();
  u64 z = pack2(0.f, 0.f);
  u64 acc[32];
  #pragma unroll
  for (int cc = 0; cc < 32; cc++) acc[cc] = z;
  float l = 0.f;
  #pragma unroll 1
  for (int j = 0; j < 192; j++){
    const ulonglong2* kr = (const ulonglong2*)(Ksh + j*68);
    u64 a0 = z, a1 = z, a2 = z, a3 = z;
    #pragma unroll
    for (int cc = 0; cc < 8; cc++){
      ulonglong2 kv = kr[cc];
      ffma2((cc & 1) ? a1 : a0, q2[4*cc+0], kv.x);
      ffma2((cc & 1) ? a3 : a2, q2[4*cc+1], kv.y);
    }
    #pragma unroll
    for (int cc = 8; cc < 16; cc++){
      ulonglong2 kv = kr[cc];
      ffma2((cc & 1) ? a1 : a0, q2[2*cc+0], kv.x);
      ffma2((cc & 1) ? a3 : a2, q2[2*cc+1], kv.y);
    }
    float x0,y0,x1,y1,x2,y2,x3,y3;
    unpack2(a0,x0,y0); unpack2(a1,x1,y1); unpack2(a2,x2,y2); unpack2(a3,x3,y3);
    float s = ((x0+y0)+(x1+y1)) + ((x2+y2)+(x3+y3));
    float p = __expf(s);
    l += p;
    u64 ps = pack2(p, p);
    const ulonglong2* vr = (const ulonglong2*)(Vsh + j*68);
    #pragma unroll
    for (int cc = 0; cc < 16; cc++){
      ulonglong2 vv = vr[cc];
      ffma2(acc[2*cc],   ps, vv.x);
      ffma2(acc[2*cc+1], ps, vv.y);
    }
  }
  float gam = gamma_p[0] / l;
  #pragma unroll
  for (int cc = 0; cc < 32; cc++){
    float a0, a1; unpack2(acc[cc], a0, a1);
    Ob[(size_t)(2*cc)*NN + t]   = gam*a0 + Xb[(size_t)(2*cc)*NN + t];
    Ob[(size_t)(2*cc+1)*NN + t] = gam*a1 + Xb[(size_t)(2*cc+1)*NN + t];
  }
}

// ================= per-plane 192x192 transpose =================
__global__ void k_transpose(int in_slice, int out_slice)
{
  __shared__ float tile[32][33];
  const float* in = g_scratch + (size_t)in_slice*NELEM + (size_t)blockIdx.z*NN;
  float* out      = g_scratch + (size_t)out_slice*NELEM + (size_t)blockIdx.z*NN;
  int x0 = blockIdx.x*32, y0 = blockIdx.y*32;
  int tx = threadIdx.x, ty = threadIdx.y;
  #pragma unroll
  for (int k = 0; k < 32; k += 8)
    tile[ty+k][tx] = in[(size_t)(y0+ty+k)*WW + x0+tx];
  __syncthreads();
  #pragma unroll
  for (int k = 0; k < 32; k += 8)
    out[(size_t)(x0+ty+k)*HH + y0+tx] = tile[tx][ty+k];
}

extern "C" void kernel_launch(void* const* d_in, const int* in_sizes, int n_in,
                              void* d_out, int out_size)
{
  const float* x    = (const float*)d_in[0];
  const float* pw_w = (const float*)d_in[1];
  const float* dw_w = (const float*)d_in[2];
  const float* dw_b = (const float*)d_in[3];
  const float* c2w  = (const float*)d_in[4];
  const float* c2b  = (const float*)d_in[5];
  const float* c0w  = (const float*)d_in[6];
  const float* c0b  = (const float*)d_in[7];
  const float* aq   = (const float*)d_in[8];
  const float* ak   = (const float*)d_in[9];
  const float* av   = (const float*)d_in[10];
  const float* ap   = (const float*)d_in[11];
  const float* temp = (const float*)d_in[12];
  const float* rq   = (const float*)d_in[13];
  const float* rk   = (const float*)d_in[14];
  const float* rv   = (const float*)d_in[15];
  const float* rg   = (const float*)d_in[16];
  const float* cq   = (const float*)d_in[17];
  const float* ck   = (const float*)d_in[18];
  const float* cv   = (const float*)d_in[19];
  const float* cg   = (const float*)d_in[20];
  const float* fw   = (const float*)d_in[21];
  const float* fb   = (const float*)d_in[22];
  float* out = (float*)d_out;

  const int TILES = (BATCH*NN)/TP;                 // 1152
  const int SM_C1 = (64*TP + 64*68)*4;             // 50176
  const int SM_C2 = (64*TP + 2*64*68)*4;           // 67584
  const int SM_DI = (2*64*TP + 2*64*68)*4;         // 100352
  const int SM_F3 = (64*TP + 192*68)*4;            // 85000ish
  const int SM_AP = (64*TP + 64*36)*4;             // 41984
  const int SM_LA = 2*192*68*4;                    // 104448
  cudaFuncSetAttribute(k_conv1,  cudaFuncAttributeMaxDynamicSharedMemorySize, SM_C1);
  cudaFuncSetAttribute(k_conv2,  cudaFuncAttributeMaxDynamicSharedMemorySize, SM_C2);
  cudaFuncSetAttribute(k_convDI, cudaFuncAttributeMaxDynamicSharedMemorySize, SM_DI);
  cudaFuncSetAttribute(k_final3, cudaFuncAttributeMaxDynamicSharedMemorySize, SM_F3);
  cudaFuncSetAttribute(k_apply_t,cudaFuncAttributeMaxDynamicSharedMemorySize, SM_AP);
  cudaFuncSetAttribute(k_lineattn,cudaFuncAttributeMaxDynamicSharedMemorySize, SM_LA);

  // t = pw(x); gelu(dw(t)+b); x1 = conv2(u)+b2 + conv0(x)+b0
  k_conv1<<<TILES,256,SM_C1>>>(x, -1, nullptr, 0, pw_w, 64, nullptr, 0);
  k_dwgelu<<<NELEM/256,256>>>(0, 1, dw_w, dw_b);
  k_convDI<<<TILES,256,SM_DI>>>(1, x, 2, c2w, c2b, c0w, c0b);

  // channel attention -> out1 (slice 7)
  k_conv2<<<TILES,256,SM_C2>>>(2, 3, 4, aq, ak);
  k_conv1<<<TILES,256,SM_C1>>>(nullptr, 2, nullptr, 5, av, 64, nullptr, 0);
  k_gram<<<512,256>>>(3, 4);
  k_attnsoft<<<8,1024>>>(temp);
  k_apply_t<<<TILES,256,SM_AP>>>(5, 6);
  k_conv1<<<TILES,256,SM_C1>>>(nullptr, 6, nullptr, 7, ap, 64, nullptr, 0);

  // row attention -> out2 (slice 8)
  k_conv2<<<TILES,256,SM_C2>>>(2, 3, 4, rq, rk);
  k_conv1<<<TILES,256,SM_C1>>>(nullptr, 7, nullptr, 5, rv, 64, nullptr, 0);
  k_lineattn<<<768,192,SM_LA>>>(3, 4, 5, 2, 8, rg);

  // col attention -> out3 (slice 9), via transposed planes
  k_conv2<<<TILES,256,SM_C2>>>(2, 3, 4, cq, ck);
  k_conv1<<<TILES,256,SM_C1>>>(nullptr, 7, nullptr, 5, cv, 64, nullptr, 0);
  dim3 tg(6,6,BATCH*CC), tb(32,8);
  k_transpose<<<tg,tb>>>(3, 0);
  k_transpose<<<tg,tb>>>(4, 1);
  k_transpose<<<tg,tb>>>(5, 6);
  k_transpose<<<tg,tb>>>(2, 10);
  k_lineattn<<<768,192,SM_LA>>>(0, 1, 6, 10, 3, cg);
  k_transpose<<<tg,tb>>>(3, 9);

  // fuse
  k_final3<<<TILES,256,SM_F3>>>(7, 8, 9, fw, fb, out);
}